// round 10
// baseline (speedup 1.0000x reference)
#include <cuda_runtime.h>
#include <cuda_fp16.h>
#include <math.h>
#include <stdint.h>

// ---------------------------------------------------------------------------
// ShiftedWindowAttention (B=32, 64x64, C=256, 8 heads x 32, ws=8, shift=4)
//
// K0: x (gathered+rolled) -> fp16; w_qkv, w_out -> fp16
// K1: qkv GEMM -> g_q (scale folded) / g_k / g_v fp16 planes
// K2: FUSED per-window kernel: attention (8 warps = 8 heads, HMMA,
//     register softmax) -> att in smem -> out-projection GEMM (w_out
//     streamed via cp.async) -> bias + inverse-roll scatter, f32 out.
// ---------------------------------------------------------------------------

#define KDIM 256
typedef __half fp16;

__device__ fp16  g_x2  [131072UL * 256];   // x gathered, fp16
__device__ fp16  g_q   [131072UL * 256];   // q scaled
__device__ fp16  g_k   [131072UL * 256];
__device__ fp16  g_v   [131072UL * 256];
__device__ fp16  g_w2  [768 * 256];        // w_qkv
__device__ fp16  g_w3  [256 * 256];        // w_out

static __device__ __constant__ float SCALEF = 0.17677669529663687f;  // 32^-0.5

__device__ __forceinline__ int gather_off(int gm) {
    int w  = gm >> 6;
    int t  = gm & 63;
    int b  = w >> 6;
    int wl = w & 63;
    int r  = ((wl >> 3) << 3) + (t >> 3);
    int c  = ((wl & 7) << 3) + (t & 7);
    int sr = (r + 4) & 63;
    int sc = (c + 4) & 63;
    return (b * 4096 + sr * 64 + sc) * KDIM;
}

#define SWZ(off) ((off) ^ (((off) >> 3) & 0x70))

__device__ __forceinline__ uint32_t smem_u32(const void* p) {
    uint32_t a;
    asm("{ .reg .u64 t; cvta.to.shared.u64 t, %1; cvt.u32.u64 %0, t; }"
        : "=r"(a) : "l"(p));
    return a;
}

#define LDSM4(r, addr)                                                         \
    asm volatile("ldmatrix.sync.aligned.m8n8.x4.shared.b16 {%0,%1,%2,%3}, [%4];"\
                 : "=r"((r)[0]), "=r"((r)[1]), "=r"((r)[2]), "=r"((r)[3])      \
                 : "r"(addr))

#define MMA16816(d, a, b)                                                      \
    asm volatile("mma.sync.aligned.m16n8k16.row.col.f32.f16.f16.f32 "          \
                 "{%0,%1,%2,%3}, {%4,%5,%6,%7}, {%8,%9}, {%0,%1,%2,%3};"       \
                 : "+f"((d)[0]), "+f"((d)[1]), "+f"((d)[2]), "+f"((d)[3])      \
                 : "r"((a)[0]), "r"((a)[1]), "r"((a)[2]), "r"((a)[3]),         \
                   "r"((b)[0]), "r"((b)[1]))

__device__ __forceinline__ uint32_t packh(float lo, float hi) {
    __half2 h = __floats2half2_rn(lo, hi);
    return *(uint32_t*)&h;
}

// ---------------------------------------------------------------------------
// K0: conversion. mode 0: x (gathered) -> g_x2
//                 mode 1: w_qkv -> g_w2,  mode 2: w_out -> g_w3
// ---------------------------------------------------------------------------
__global__ void convert_kernel(const float* __restrict__ src, int nrows, int mode)
{
    int idx = blockIdx.x * blockDim.x + threadIdx.x;
    if (idx >= nrows * 64) return;
    int row = idx >> 6;
    int c   = (idx & 63) << 2;
    const float* sp = src + (mode == 0 ? gather_off(row) : row * 256) + c;
    float4 v = *(const float4*)sp;

    fp16 __align__(8) hi[4];
    hi[0] = __float2half_rn(v.x);
    hi[1] = __float2half_rn(v.y);
    hi[2] = __float2half_rn(v.z);
    hi[3] = __float2half_rn(v.w);

    fp16* dst = (mode == 0) ? g_x2 : ((mode == 1) ? g_w2 : g_w3);
    *(uint2*)(dst + (size_t)row * 256 + c) = *(uint2*)hi;
}

// ---------------------------------------------------------------------------
// K1: qkv GEMM.  C[128 x 128] per CTA, 8 warps, warp tile 64x32.
// K = 256 = 4 chunks of 64 cols, 2-stage cp.async pipeline.
// Epilogue writes fp16 planes g_q (scaled) / g_k / g_v.
// ---------------------------------------------------------------------------
__global__ __launch_bounds__(256, 2) void qkv_gemm(const float* __restrict__ bias)
{
    extern __shared__ __align__(1024) char smem[];

    const int tid  = threadIdx.x;
    const int lane = tid & 31;
    const int warp = tid >> 5;
    const int m0   = blockIdx.y * 128;
    const int n0c  = blockIdx.x * 128;
    const uint32_t sbase = smem_u32(smem);

    auto stage = [&](int c, int buf) {
        int kin = c * 64;
        uint32_t ab = sbase + buf * 32768;
        uint32_t bb = ab + 16384;
        #pragma unroll
        for (int i = 0; i < 4; i++) {
            int idx = tid + i * 256;
            int r  = idx >> 3;
            int ch = idx & 7;
            uint32_t off = (uint32_t)(r * 128 + ch * 16);
            const fp16* as = g_x2 + (size_t)(m0 + r) * 256 + kin + ch * 8;
            const fp16* bs = g_w2 + (size_t)(n0c + r) * 256 + kin + ch * 8;
            asm volatile("cp.async.cg.shared.global [%0], [%1], 16;"
                         :: "r"(ab + SWZ(off)), "l"(as));
            asm volatile("cp.async.cg.shared.global [%0], [%1], 16;"
                         :: "r"(bb + SWZ(off)), "l"(bs));
        }
        asm volatile("cp.async.commit_group;");
    };

    float d[4][4][4];
    #pragma unroll
    for (int mt = 0; mt < 4; mt++)
        #pragma unroll
        for (int nt = 0; nt < 4; nt++)
            #pragma unroll
            for (int j = 0; j < 4; j++) d[mt][nt][j] = 0.f;

    const int wm0 = (warp >> 2) * 64;
    const int wn0 = (warp & 3) * 32;

    stage(0, 0);
    #pragma unroll 1
    for (int c = 0; c < 4; c++) {
        if (c < 3) {
            stage(c + 1, (c + 1) & 1);
            asm volatile("cp.async.wait_group 1;");
        } else {
            asm volatile("cp.async.wait_group 0;");
        }
        __syncthreads();

        uint32_t ab = sbase + (c & 1) * 32768;
        uint32_t bb = ab + 16384;

        #pragma unroll
        for (int ks = 0; ks < 4; ks++) {
            uint32_t a[4][4], b[4][2];
            #pragma unroll
            for (int mt = 0; mt < 4; mt++) {
                int row = wm0 + mt * 16 + (lane & 15);
                int col = ks * 16 + ((lane >> 1) & 8);
                uint32_t off = (uint32_t)(row * 128 + col * 2);
                LDSM4(a[mt], ab + SWZ(off));
            }
            #pragma unroll
            for (int np = 0; np < 2; np++) {
                int row = wn0 + np * 16 + (lane & 7) + ((lane & 16) ? 8 : 0);
                int col = ks * 16 + ((lane & 8) ? 8 : 0);
                uint32_t off = (uint32_t)(row * 128 + col * 2);
                uint32_t t[4];
                LDSM4(t, bb + SWZ(off));
                b[2 * np][0] = t[0]; b[2 * np][1] = t[1];
                b[2 * np + 1][0] = t[2]; b[2 * np + 1][1] = t[3];
            }
            #pragma unroll
            for (int mt = 0; mt < 4; mt++)
                #pragma unroll
                for (int nt = 0; nt < 4; nt++)
                    MMA16816(d[mt][nt], a[mt], b[nt]);
        }
        if (c < 3) __syncthreads();
    }

    const int cc0 = n0c + wn0 + (lane & 3) * 2;
    fp16* dst   = (n0c < 256) ? g_q : ((n0c < 512) ? g_k : g_v);
    int   cbase = (n0c < 256) ? 0   : ((n0c < 512) ? 256 : 512);
    const float scl = (n0c < 256) ? SCALEF : 1.0f;
    #pragma unroll
    for (int mt = 0; mt < 4; mt++) {
        int g0 = m0 + wm0 + mt * 16 + (lane >> 2);
        #pragma unroll
        for (int nt = 0; nt < 4; nt++) {
            int col = cc0 + nt * 8;
            float bx = bias[col], by = bias[col + 1];
            float v0 = (d[mt][nt][0] + bx) * scl, v1 = (d[mt][nt][1] + by) * scl;
            float v2 = (d[mt][nt][2] + bx) * scl, v3 = (d[mt][nt][3] + by) * scl;
            int cc = col - cbase;
            *(uint32_t*)(dst + (size_t)g0 * 256 + cc)       = packh(v0, v1);
            *(uint32_t*)(dst + (size_t)(g0 + 8) * 256 + cc) = packh(v2, v3);
        }
    }
}

// ---------------------------------------------------------------------------
// K2: FUSED attention + out-projection.  One CTA per window, 256 threads.
// Phase 1: warp wp = head wp; attention over the window's 64 tokens,
//          per-head output written (fp16) into the q smem buffer (att).
// Phase 2: out = att @ w_out^T + b_out, w_out streamed via cp.async into
//          the dead k/v buffers; rows scattered by inverse roll, f32.
// smem: q 64x264 (33792B) | k 64x264 (33792B) | v 256x72 (36864B)
//       | pe 8x225 f32 (7200B) | rg 64 int (256B)   = 111904 B
// ---------------------------------------------------------------------------
__global__ __launch_bounds__(256, 2) void attn_out_kernel(
    const float* __restrict__ pos_enc,
    const float* __restrict__ b_out,
    float* __restrict__ Cout)
{
    extern __shared__ __align__(1024) char smem[];
    fp16*  q  = (fp16*)(smem);
    fp16*  kk = (fp16*)(smem + 33792);
    fp16*  vv = (fp16*)(smem + 67584);
    float* pe = (float*)(smem + 104448);
    int*   rg = (int*)(smem + 111648);

    const int w    = blockIdx.x;
    const int tid  = threadIdx.x;
    const int lane = tid & 31;
    const int wp   = tid >> 5;          // head id
    const uint32_t sb = smem_u32(smem);
    const uint32_t uq = sb, uk = sb + 33792, uv = sb + 67584;
    const size_t rowbase = (size_t)w * 64;

    // ---- fill: q/k full rows, v transposed [dim][token] ----
    for (int t = tid; t < 2048; t += 256) {
        int i = t >> 5, s = (t & 31) * 8;
        *(uint4*)(q  + i * 264 + s) = *(const uint4*)(g_q + (rowbase + i) * 256 + s);
        *(uint4*)(kk + i * 264 + s) = *(const uint4*)(g_k + (rowbase + i) * 256 + s);
        fp16 tmp[8];
        *(uint4*)tmp = *(const uint4*)(g_v + (rowbase + i) * 256 + s);
        #pragma unroll
        for (int e = 0; e < 8; e++) vv[(s + e) * 72 + i] = tmp[e];
    }
    for (int t = tid; t < 1800; t += 256) pe[t] = pos_enc[t];
    if (tid < 64) {
        int wl = w & 63;
        int r  = ((wl >> 3) << 3) + (tid >> 3);
        int c  = ((wl & 7) << 3) + (tid & 7);
        int rr = (r < 56) ? 0 : ((r < 60) ? 1 : 2);
        int cc = (c < 56) ? 0 : ((c < 60) ? 1 : 2);
        rg[tid] = rr * 3 + cc;
    }
    __syncthreads();

    const float* pew = pe + wp * 225;
    const int hc = wp * 32;             // head column base

    // ---- phase 1: attention, 4 query segments of 16 rows ----
    #pragma unroll 1
    for (int qseg = 0; qseg < 4; qseg++) {
        float c[8][4];
        #pragma unroll
        for (int j = 0; j < 8; j++)
            #pragma unroll
            for (int x = 0; x < 4; x++) c[j][x] = 0.f;

        uint32_t aq[2][4];
        #pragma unroll
        for (int ks = 0; ks < 2; ks++) {
            uint32_t off = (uint32_t)((qseg * 16 + (lane & 15)) * 528 +
                                      (hc + ks * 16 + ((lane >> 1) & 8)) * 2);
            LDSM4(aq[ks], uq + off);
        }
        #pragma unroll
        for (int np = 0; np < 4; np++) {
            #pragma unroll
            for (int ks = 0; ks < 2; ks++) {
                uint32_t off = (uint32_t)((np * 16 + (lane & 7) + ((lane & 16) ? 8 : 0)) * 528 +
                                          (hc + ks * 16 + ((lane & 8) ? 8 : 0)) * 2);
                uint32_t bh[4];
                LDSM4(bh, uk + off);
                MMA16816(c[2 * np],     aq[ks], &bh[0]);
                MMA16816(c[2 * np + 1], aq[ks], &bh[2]);
            }
        }

        // bias + mask + softmax
        const int r0 = qseg * 16 + (lane >> 2);
        const int r1 = r0 + 8;
        const int yi0 = r0 >> 3, xi0 = r0 & 7, ri0 = rg[r0];
        const int yi1 = r1 >> 3, xi1 = r1 & 7, ri1 = rg[r1];
        float mx0 = -INFINITY, mx1 = -INFINITY;
        #pragma unroll
        for (int j = 0; j < 8; j++) {
            #pragma unroll
            for (int dd = 0; dd < 2; dd++) {
                int col = j * 8 + (lane & 3) * 2 + dd;
                int yj = col >> 3, xj = col & 7;
                int rc = rg[col];
                c[j][dd]     = (rc == ri0)
                    ? c[j][dd]     + pew[(yi0 - yj + 7) * 15 + (xi0 - xj + 7)] : -INFINITY;
                c[j][dd + 2] = (rc == ri1)
                    ? c[j][dd + 2] + pew[(yi1 - yj + 7) * 15 + (xi1 - xj + 7)] : -INFINITY;
                mx0 = fmaxf(mx0, c[j][dd]);
                mx1 = fmaxf(mx1, c[j][dd + 2]);
            }
        }
        mx0 = fmaxf(mx0, __shfl_xor_sync(0xffffffffu, mx0, 1));
        mx0 = fmaxf(mx0, __shfl_xor_sync(0xffffffffu, mx0, 2));
        mx1 = fmaxf(mx1, __shfl_xor_sync(0xffffffffu, mx1, 1));
        mx1 = fmaxf(mx1, __shfl_xor_sync(0xffffffffu, mx1, 2));
        float s0 = 0.f, s1 = 0.f;
        #pragma unroll
        for (int j = 0; j < 8; j++) {
            #pragma unroll
            for (int dd = 0; dd < 2; dd++) {
                c[j][dd]     = __expf(c[j][dd] - mx0);     s0 += c[j][dd];
                c[j][dd + 2] = __expf(c[j][dd + 2] - mx1); s1 += c[j][dd + 2];
            }
        }
        s0 += __shfl_xor_sync(0xffffffffu, s0, 1);
        s0 += __shfl_xor_sync(0xffffffffu, s0, 2);
        s1 += __shfl_xor_sync(0xffffffffu, s1, 1);
        s1 += __shfl_xor_sync(0xffffffffu, s1, 2);
        const float inv0 = 1.0f / s0, inv1 = 1.0f / s1;

        // repack P (C-frag -> A-frag)
        uint32_t ph[4][4];
        #pragma unroll
        for (int t = 0; t < 4; t++) {
            #pragma unroll
            for (int x = 0; x < 4; x++) {
                int nt = 2 * t + (x >> 1);
                int p0 = (x & 1) * 2;
                float iv = (p0 == 0) ? inv0 : inv1;
                ph[t][x] = packh(c[nt][p0] * iv, c[nt][p0 + 1] * iv);
            }
        }

        // O = P v
        float o[4][4];
        #pragma unroll
        for (int nt = 0; nt < 4; nt++)
            #pragma unroll
            for (int x = 0; x < 4; x++) o[nt][x] = 0.f;

        #pragma unroll
        for (int t = 0; t < 4; t++) {
            #pragma unroll
            for (int nb = 0; nb < 2; nb++) {
                uint32_t off = (uint32_t)((hc + nb * 16 + (lane & 7) + ((lane & 16) ? 8 : 0)) * 144 +
                                          (t * 16 + ((lane & 8) ? 8 : 0)) * 2);
                uint32_t bh[4];
                LDSM4(bh, uv + off);
                MMA16816(o[2 * nb],     ph[t], &bh[0]);
                MMA16816(o[2 * nb + 1], ph[t], &bh[2]);
            }
        }

        // write per-head output into att (overlays q; rows of this qseg only)
        #pragma unroll
        for (int nt = 0; nt < 4; nt++) {
            int d0 = hc + nt * 8 + (lane & 3) * 2;
            *(uint32_t*)(q + r0 * 264 + d0) = packh(o[nt][0], o[nt][1]);
            *(uint32_t*)(q + r1 * 264 + d0) = packh(o[nt][2], o[nt][3]);
        }
    }
    __syncthreads();

    // ---- phase 2: out-projection + scatter ----
    auto stage = [&](int c, int buf) {
        uint32_t bb = buf ? uv : uk;
        #pragma unroll
        for (int i = 0; i < 8; i++) {
            int idx = tid + i * 256;
            int r  = idx >> 3;
            int ch = idx & 7;
            const fp16* src = g_w3 + (size_t)r * 256 + c * 64 + ch * 8;
            asm volatile("cp.async.cg.shared.global [%0], [%1], 16;"
                         :: "r"(bb + SWZ((uint32_t)(r * 128 + ch * 16))), "l"(src));
        }
        asm volatile("cp.async.commit_group;");
    };

    float d[4][4][4];
    #pragma unroll
    for (int mt = 0; mt < 4; mt++)
        #pragma unroll
        for (int nt = 0; nt < 4; nt++)
            #pragma unroll
            for (int j = 0; j < 4; j++) d[mt][nt][j] = 0.f;

    stage(0, 0);
    #pragma unroll 1
    for (int ch = 0; ch < 4; ch++) {
        if (ch < 3) {
            stage(ch + 1, (ch + 1) & 1);
            asm volatile("cp.async.wait_group 1;");
        } else {
            asm volatile("cp.async.wait_group 0;");
        }
        __syncthreads();

        uint32_t bb = (ch & 1) ? uv : uk;
        #pragma unroll
        for (int ks = 0; ks < 4; ks++) {
            uint32_t a[4][4], b[4][2];
            #pragma unroll
            for (int mt = 0; mt < 4; mt++) {
                int row = mt * 16 + (lane & 15);
                int col = ch * 64 + ks * 16 + ((lane >> 1) & 8);
                LDSM4(a[mt], uq + (uint32_t)(row * 528 + col * 2));
            }
            #pragma unroll
            for (int np = 0; np < 2; np++) {
                int row = wp * 32 + np * 16 + (lane & 7) + ((lane & 16) ? 8 : 0);
                int col = ks * 16 + ((lane & 8) ? 8 : 0);
                uint32_t t4[4];
                LDSM4(t4, bb + SWZ((uint32_t)(row * 128 + col * 2)));
                b[2 * np][0] = t4[0]; b[2 * np][1] = t4[1];
                b[2 * np + 1][0] = t4[2]; b[2 * np + 1][1] = t4[3];
            }
            #pragma unroll
            for (int mt = 0; mt < 4; mt++)
                #pragma unroll
                for (int nt = 0; nt < 4; nt++)
                    MMA16816(d[mt][nt], a[mt], b[nt]);
        }
        if (ch < 3) __syncthreads();
    }

    const int cc0 = wp * 32 + (lane & 3) * 2;
    #pragma unroll
    for (int mt = 0; mt < 4; mt++) {
        int lr = mt * 16 + (lane >> 2);
        size_t ob0 = (size_t)gather_off(w * 64 + lr);
        size_t ob1 = (size_t)gather_off(w * 64 + lr + 8);
        #pragma unroll
        for (int nt = 0; nt < 4; nt++) {
            int col = cc0 + nt * 8;
            float bx = b_out[col], by = b_out[col + 1];
            float2 o0 = {d[mt][nt][0] + bx, d[mt][nt][1] + by};
            float2 o1 = {d[mt][nt][2] + bx, d[mt][nt][3] + by};
            *(float2*)(Cout + ob0 + col) = o0;
            *(float2*)(Cout + ob1 + col) = o1;
        }
    }
}

// ---------------------------------------------------------------------------
extern "C" void kernel_launch(void* const* d_in, const int* in_sizes, int n_in,
                              void* d_out, int out_size)
{
    const float* x     = (const float*)d_in[0];
    const float* w_qkv = (const float*)d_in[1];
    const float* b_qkv = (const float*)d_in[2];
    const float* w_out = (const float*)d_in[3];
    const float* b_out = (const float*)d_in[4];
    const float* pos   = (const float*)d_in[5];
    float* out = (float*)d_out;

    const int SMEM1 = 65536;
    const int SMEM2 = 111904;
    cudaFuncSetAttribute(qkv_gemm,
                         cudaFuncAttributeMaxDynamicSharedMemorySize, SMEM1);
    cudaFuncSetAttribute(attn_out_kernel,
                         cudaFuncAttributeMaxDynamicSharedMemorySize, SMEM2);

    convert_kernel<<<32768, 256>>>(x, 131072, 0);
    convert_kernel<<<192,   256>>>(w_qkv, 768, 1);
    convert_kernel<<<64,    256>>>(w_out, 256, 2);
    qkv_gemm<<<dim3(6, 1024), 256, SMEM1>>>(b_qkv);
    attn_out_kernel<<<2048, 256, SMEM2>>>(pos, b_out, out);
}

// round 13
// speedup vs baseline: 1.2723x; 1.2723x over previous
#include <cuda_runtime.h>
#include <cuda_fp16.h>
#include <math.h>
#include <stdint.h>

// ---------------------------------------------------------------------------
// ShiftedWindowAttention (B=32, 64x64, C=256, 8 heads x 32, ws=8, shift=4)
//
// R9 structure (best: 360.5us), with head-blocked qkv layout:
//   g_q/g_k/g_v stored as [head][row][32] so each attention CTA reads
//   contiguous 4KB blocks instead of 64B slices strided 512B.
// K0: x (gathered+rolled) -> fp16; w_qkv + w_out -> fp16 (one kernel)
// K1: qkv GEMM -> g_q (scale folded) / g_k / g_v, head-blocked fp16
// K2: per-(window,head) attention, HMMA, register softmax -> g_att2 fp16
// K3: out = att2 @ w_out^T + b_out, inverse-roll scatter, f32
// (Resubmission of R11 — previous bench died to container infra, not kernel.)
// ---------------------------------------------------------------------------

#define KDIM 256
typedef __half fp16;

#define HPLANE 4194304UL   // 131072 * 32 elements per head plane

__device__ fp16  g_x2  [131072UL * 256];   // x gathered, fp16
__device__ fp16  g_q   [131072UL * 256];   // [head][row][32], scale folded
__device__ fp16  g_k   [131072UL * 256];   // [head][row][32]
__device__ fp16  g_v   [131072UL * 256];   // [head][row][32]
__device__ fp16  g_att2[131072UL * 256];   // attention out, row-major [row][256]
__device__ fp16  g_w2  [768 * 256];        // w_qkv
__device__ fp16  g_w3  [256 * 256];        // w_out

static __device__ __constant__ float SCALEF = 0.17677669529663687f;  // 32^-0.5

__device__ __forceinline__ int gather_off(int gm) {
    int w  = gm >> 6;
    int t  = gm & 63;
    int b  = w >> 6;
    int wl = w & 63;
    int r  = ((wl >> 3) << 3) + (t >> 3);
    int c  = ((wl & 7) << 3) + (t & 7);
    int sr = (r + 4) & 63;
    int sc = (c + 4) & 63;
    return (b * 4096 + sr * 64 + sc) * KDIM;
}

#define SWZ(off) ((off) ^ (((off) >> 3) & 0x70))

__device__ __forceinline__ uint32_t smem_u32(const void* p) {
    uint32_t a;
    asm("{ .reg .u64 t; cvta.to.shared.u64 t, %1; cvt.u32.u64 %0, t; }"
        : "=r"(a) : "l"(p));
    return a;
}

#define LDSM4(r, addr)                                                         \
    asm volatile("ldmatrix.sync.aligned.m8n8.x4.shared.b16 {%0,%1,%2,%3}, [%4];"\
                 : "=r"((r)[0]), "=r"((r)[1]), "=r"((r)[2]), "=r"((r)[3])      \
                 : "r"(addr))

#define MMA16816(d, a, b)                                                      \
    asm volatile("mma.sync.aligned.m16n8k16.row.col.f32.f16.f16.f32 "          \
                 "{%0,%1,%2,%3}, {%4,%5,%6,%7}, {%8,%9}, {%0,%1,%2,%3};"       \
                 : "+f"((d)[0]), "+f"((d)[1]), "+f"((d)[2]), "+f"((d)[3])      \
                 : "r"((a)[0]), "r"((a)[1]), "r"((a)[2]), "r"((a)[3]),         \
                   "r"((b)[0]), "r"((b)[1]))

__device__ __forceinline__ uint32_t packh(float lo, float hi) {
    __half2 h = __floats2half2_rn(lo, hi);
    return *(uint32_t*)&h;
}

// ---------------------------------------------------------------------------
// K0a: x (gathered) -> g_x2 fp16
// ---------------------------------------------------------------------------
__global__ void convert_x(const float* __restrict__ src)
{
    int idx = blockIdx.x * blockDim.x + threadIdx.x;
    int row = idx >> 6;
    int c   = (idx & 63) << 2;
    float4 v = *(const float4*)(src + gather_off(row) + c);

    fp16 __align__(8) hi[4];
    hi[0] = __float2half_rn(v.x);
    hi[1] = __float2half_rn(v.y);
    hi[2] = __float2half_rn(v.z);
    hi[3] = __float2half_rn(v.w);
    *(uint2*)(g_x2 + (size_t)row * 256 + c) = *(uint2*)hi;
}

// K0b: both weight matrices -> fp16 in one launch
__global__ void convert_w(const float* __restrict__ wq, const float* __restrict__ wo)
{
    int idx = blockIdx.x * blockDim.x + threadIdx.x;   // 1024*64
    int row = idx >> 6;
    int c   = (idx & 63) << 2;
    const float* sp;
    fp16* dst;
    if (row < 768) { sp = wq + row * 256 + c;        dst = g_w2 + (size_t)row * 256 + c; }
    else           { sp = wo + (row - 768) * 256 + c; dst = g_w3 + (size_t)(row - 768) * 256 + c; }
    float4 v = *(const float4*)sp;
    fp16 __align__(8) hi[4];
    hi[0] = __float2half_rn(v.x);
    hi[1] = __float2half_rn(v.y);
    hi[2] = __float2half_rn(v.z);
    hi[3] = __float2half_rn(v.w);
    *(uint2*)dst = *(uint2*)hi;
}

// ---------------------------------------------------------------------------
// mma.sync GEMM.  C[128 x 128] per CTA, 8 warps, warp tile 64x32.
// K = 256 = 4 chunks of 64 cols, 2-stage cp.async pipeline.
// !SCATTER: epilogue writes head-blocked fp16 planes g_q (scaled)/g_k/g_v.
// SCATTER:  f32 output, inverse-roll row scatter (A = g_att2 row-major).
// ---------------------------------------------------------------------------
template <int NT, bool SCATTER>
__global__ __launch_bounds__(256, 2) void mma_gemm(const float* __restrict__ bias,
                                                   float* __restrict__ Cout)
{
    extern __shared__ __align__(1024) char smem[];
    const fp16* Ag = SCATTER ? g_att2 : g_x2;
    const fp16* Bg = SCATTER ? g_w3   : g_w2;

    const int tid  = threadIdx.x;
    const int lane = tid & 31;
    const int warp = tid >> 5;
    const int m0   = blockIdx.y * 128;
    const int n0c  = blockIdx.x * 128;
    const uint32_t sbase = smem_u32(smem);

    auto stage = [&](int c, int buf) {
        int kin = c * 64;
        uint32_t ab = sbase + buf * 32768;
        uint32_t bb = ab + 16384;
        #pragma unroll
        for (int i = 0; i < 4; i++) {
            int idx = tid + i * 256;
            int r  = idx >> 3;
            int ch = idx & 7;
            uint32_t off = (uint32_t)(r * 128 + ch * 16);
            const fp16* as = Ag + (size_t)(m0 + r) * 256 + kin + ch * 8;
            const fp16* bs = Bg + (size_t)(n0c + r) * 256 + kin + ch * 8;
            asm volatile("cp.async.cg.shared.global [%0], [%1], 16;"
                         :: "r"(ab + SWZ(off)), "l"(as));
            asm volatile("cp.async.cg.shared.global [%0], [%1], 16;"
                         :: "r"(bb + SWZ(off)), "l"(bs));
        }
        asm volatile("cp.async.commit_group;");
    };

    float d[4][4][4];
    #pragma unroll
    for (int mt = 0; mt < 4; mt++)
        #pragma unroll
        for (int nt = 0; nt < 4; nt++)
            #pragma unroll
            for (int j = 0; j < 4; j++) d[mt][nt][j] = 0.f;

    const int wm0 = (warp >> 2) * 64;
    const int wn0 = (warp & 3) * 32;

    stage(0, 0);
    #pragma unroll 1
    for (int c = 0; c < 4; c++) {
        if (c < 3) {
            stage(c + 1, (c + 1) & 1);
            asm volatile("cp.async.wait_group 1;");
        } else {
            asm volatile("cp.async.wait_group 0;");
        }
        __syncthreads();

        uint32_t ab = sbase + (c & 1) * 32768;
        uint32_t bb = ab + 16384;

        #pragma unroll
        for (int ks = 0; ks < 4; ks++) {
            uint32_t a[4][4], b[4][2];
            #pragma unroll
            for (int mt = 0; mt < 4; mt++) {
                int row = wm0 + mt * 16 + (lane & 15);
                int col = ks * 16 + ((lane >> 1) & 8);
                uint32_t off = (uint32_t)(row * 128 + col * 2);
                LDSM4(a[mt], ab + SWZ(off));
            }
            #pragma unroll
            for (int np = 0; np < 2; np++) {
                int row = wn0 + np * 16 + (lane & 7) + ((lane & 16) ? 8 : 0);
                int col = ks * 16 + ((lane & 8) ? 8 : 0);
                uint32_t off = (uint32_t)(row * 128 + col * 2);
                uint32_t t[4];
                LDSM4(t, bb + SWZ(off));
                b[2 * np][0] = t[0]; b[2 * np][1] = t[1];
                b[2 * np + 1][0] = t[2]; b[2 * np + 1][1] = t[3];
            }
            #pragma unroll
            for (int mt = 0; mt < 4; mt++)
                #pragma unroll
                for (int nt = 0; nt < 4; nt++)
                    MMA16816(d[mt][nt], a[mt], b[nt]);
        }
        if (c < 3) __syncthreads();
    }

    const int cc0 = n0c + wn0 + (lane & 3) * 2;
    if (SCATTER) {
        #pragma unroll
        for (int mt = 0; mt < 4; mt++) {
            int g0 = m0 + wm0 + mt * 16 + (lane >> 2);
            size_t ob0 = (size_t)gather_off(g0);
            size_t ob1 = (size_t)gather_off(g0 + 8);
            #pragma unroll
            for (int nt = 0; nt < 4; nt++) {
                int col = cc0 + nt * 8;
                float bx = bias[col], by = bias[col + 1];
                float2 o0 = {d[mt][nt][0] + bx, d[mt][nt][1] + by};
                float2 o1 = {d[mt][nt][2] + bx, d[mt][nt][3] + by};
                *(float2*)(Cout + ob0 + col) = o0;
                *(float2*)(Cout + ob1 + col) = o1;
            }
        }
    } else {
        fp16* dst   = (n0c < 256) ? g_q : ((n0c < 512) ? g_k : g_v);
        int   cbase = (n0c < 256) ? 0   : ((n0c < 512) ? 256 : 512);
        const float scl = (n0c < 256) ? SCALEF : 1.0f;
        #pragma unroll
        for (int mt = 0; mt < 4; mt++) {
            int g0 = m0 + wm0 + mt * 16 + (lane >> 2);
            #pragma unroll
            for (int nt = 0; nt < 4; nt++) {
                int col = cc0 + nt * 8;
                float bx = bias[col], by = bias[col + 1];
                float v0 = (d[mt][nt][0] + bx) * scl, v1 = (d[mt][nt][1] + by) * scl;
                float v2 = (d[mt][nt][2] + bx) * scl, v3 = (d[mt][nt][3] + by) * scl;
                int cc  = col - cbase;        // 0..255
                size_t hb = (size_t)(cc >> 5) * HPLANE + (cc & 31);
                *(uint32_t*)(dst + hb + (size_t)g0 * 32)       = packh(v0, v1);
                *(uint32_t*)(dst + hb + (size_t)(g0 + 8) * 32) = packh(v2, v3);
            }
        }
    }
}

// ---------------------------------------------------------------------------
// K2: tensor-core windowed attention, single fp16 everywhere.
// One block per (window, head), 4 warps, warp = 16 query rows.
// Head-blocked qkv: per CTA three contiguous 4KB reads.
// ---------------------------------------------------------------------------
__global__ __launch_bounds__(128) void attn_kernel(const float* __restrict__ pos_enc)
{
    __shared__ fp16 qh[64 * 40];
    __shared__ fp16 kh[64 * 40];
    __shared__ fp16 vh[32 * 72];               // transposed [dim][col]
    __shared__ float pe[225];
    __shared__ int   rg[64];

    const int w    = blockIdx.x;
    const int h    = blockIdx.y;
    const int tid  = threadIdx.x;
    const int lane = tid & 31;
    const int wp   = tid >> 5;

    const size_t hb = (size_t)h * HPLANE + (size_t)(w * 64) * 32;

    for (int t = tid; t < 256; t += 128) {
        int i = t >> 2, d0 = (t & 3) * 8;
        *(uint4*)(qh + i * 40 + d0) = *(const uint4*)(g_q + hb + i * 32 + d0);
    }
    for (int t = tid; t < 256; t += 128) {
        int i = t >> 2, d0 = (t & 3) * 8;
        *(uint4*)(kh + i * 40 + d0) = *(const uint4*)(g_k + hb + i * 32 + d0);
    }
    for (int t = tid; t < 256; t += 128) {
        int i = t >> 2, d0 = (t & 3) * 8;
        fp16 tmp[8];
        *(uint4*)tmp = *(const uint4*)(g_v + hb + i * 32 + d0);
        #pragma unroll
        for (int e = 0; e < 8; e++) vh[(d0 + e) * 72 + i] = tmp[e];
    }
    for (int idx = tid; idx < 225; idx += 128) pe[idx] = pos_enc[h * 225 + idx];
    if (tid < 64) {
        int wl = w & 63;
        int r  = ((wl >> 3) << 3) + (tid >> 3);
        int c  = ((wl & 7) << 3) + (tid & 7);
        int rr = (r < 56) ? 0 : ((r < 60) ? 1 : 2);
        int cc = (c < 56) ? 0 : ((c < 60) ? 1 : 2);
        rg[tid] = rr * 3 + cc;
    }
    __syncthreads();

    const uint32_t uqh = smem_u32(qh);
    const uint32_t ukh = smem_u32(kh);
    const uint32_t uvh = smem_u32(vh);

    // ---- S = q k^T ----
    float c[8][4];
    #pragma unroll
    for (int j = 0; j < 8; j++)
        #pragma unroll
        for (int q = 0; q < 4; q++) c[j][q] = 0.f;

    uint32_t aq[2][4];
    #pragma unroll
    for (int ks = 0; ks < 2; ks++) {
        uint32_t off = (uint32_t)((wp * 16 + (lane & 15)) * 80 +
                                  (ks * 16 + ((lane >> 1) & 8)) * 2);
        LDSM4(aq[ks], uqh + off);
    }
    #pragma unroll
    for (int np = 0; np < 4; np++) {
        #pragma unroll
        for (int ks = 0; ks < 2; ks++) {
            uint32_t off = (uint32_t)((np * 16 + (lane & 7) + ((lane & 16) ? 8 : 0)) * 80 +
                                      (ks * 16 + ((lane & 8) ? 8 : 0)) * 2);
            uint32_t bh[4];
            LDSM4(bh, ukh + off);
            MMA16816(c[2 * np],     aq[ks], &bh[0]);
            MMA16816(c[2 * np + 1], aq[ks], &bh[2]);
        }
    }

    // ---- bias + mask + softmax on fragments ----
    const int r0 = wp * 16 + (lane >> 2);
    const int r1 = r0 + 8;
    const int yi0 = r0 >> 3, xi0 = r0 & 7, ri0 = rg[r0];
    const int yi1 = r1 >> 3, xi1 = r1 & 7, ri1 = rg[r1];
    float mx0 = -INFINITY, mx1 = -INFINITY;
    #pragma unroll
    for (int j = 0; j < 8; j++) {
        #pragma unroll
        for (int dd = 0; dd < 2; dd++) {
            int col = j * 8 + (lane & 3) * 2 + dd;
            int yj = col >> 3, xj = col & 7;
            int rc = rg[col];
            c[j][dd]     = (rc == ri0)
                ? c[j][dd]     + pe[(yi0 - yj + 7) * 15 + (xi0 - xj + 7)] : -INFINITY;
            c[j][dd + 2] = (rc == ri1)
                ? c[j][dd + 2] + pe[(yi1 - yj + 7) * 15 + (xi1 - xj + 7)] : -INFINITY;
            mx0 = fmaxf(mx0, c[j][dd]);
            mx1 = fmaxf(mx1, c[j][dd + 2]);
        }
    }
    mx0 = fmaxf(mx0, __shfl_xor_sync(0xffffffffu, mx0, 1));
    mx0 = fmaxf(mx0, __shfl_xor_sync(0xffffffffu, mx0, 2));
    mx1 = fmaxf(mx1, __shfl_xor_sync(0xffffffffu, mx1, 1));
    mx1 = fmaxf(mx1, __shfl_xor_sync(0xffffffffu, mx1, 2));
    float s0 = 0.f, s1 = 0.f;
    #pragma unroll
    for (int j = 0; j < 8; j++) {
        #pragma unroll
        for (int dd = 0; dd < 2; dd++) {
            c[j][dd]     = __expf(c[j][dd] - mx0);     s0 += c[j][dd];
            c[j][dd + 2] = __expf(c[j][dd + 2] - mx1); s1 += c[j][dd + 2];
        }
    }
    s0 += __shfl_xor_sync(0xffffffffu, s0, 1);
    s0 += __shfl_xor_sync(0xffffffffu, s0, 2);
    s1 += __shfl_xor_sync(0xffffffffu, s1, 1);
    s1 += __shfl_xor_sync(0xffffffffu, s1, 2);
    const float inv0 = 1.0f / s0, inv1 = 1.0f / s1;

    // ---- repack P (C-frag -> A-frag), single fp16 ----
    uint32_t ph[4][4];
    #pragma unroll
    for (int t = 0; t < 4; t++) {
        #pragma unroll
        for (int q = 0; q < 4; q++) {
            int nt = 2 * t + (q >> 1);
            int p0 = (q & 1) * 2;
            float iv = (p0 == 0) ? inv0 : inv1;
            ph[t][q] = packh(c[nt][p0] * iv, c[nt][p0 + 1] * iv);
        }
    }

    // ---- O = P v ----
    float o[4][4];
    #pragma unroll
    for (int nt = 0; nt < 4; nt++)
        #pragma unroll
        for (int q = 0; q < 4; q++) o[nt][q] = 0.f;

    #pragma unroll
    for (int t = 0; t < 4; t++) {
        #pragma unroll
        for (int nb = 0; nb < 2; nb++) {
            uint32_t off = (uint32_t)((nb * 16 + (lane & 7) + ((lane & 16) ? 8 : 0)) * 144 +
                                      (t * 16 + ((lane & 8) ? 8 : 0)) * 2);
            uint32_t bh[4];
            LDSM4(bh, uvh + off);
            MMA16816(o[2 * nb],     ph[t], &bh[0]);
            MMA16816(o[2 * nb + 1], ph[t], &bh[2]);
        }
    }

    // ---- epilogue: fp16 to g_att2 (row-major [row][256]) ----
    size_t rb0 = (size_t)(w * 64 + r0) * 256 + h * 32;
    size_t rb1 = (size_t)(w * 64 + r1) * 256 + h * 32;
    #pragma unroll
    for (int nt = 0; nt < 4; nt++) {
        int d0 = nt * 8 + (lane & 3) * 2;
        *(uint32_t*)(g_att2 + rb0 + d0) = packh(o[nt][0], o[nt][1]);
        *(uint32_t*)(g_att2 + rb1 + d0) = packh(o[nt][2], o[nt][3]);
    }
}

// ---------------------------------------------------------------------------
extern "C" void kernel_launch(void* const* d_in, const int* in_sizes, int n_in,
                              void* d_out, int out_size)
{
    const float* x     = (const float*)d_in[0];
    const float* w_qkv = (const float*)d_in[1];
    const float* b_qkv = (const float*)d_in[2];
    const float* w_out = (const float*)d_in[3];
    const float* b_out = (const float*)d_in[4];
    const float* pos   = (const float*)d_in[5];
    float* out = (float*)d_out;

    const int SMEM = 65536;
    cudaFuncSetAttribute(mma_gemm<6, false>,
                         cudaFuncAttributeMaxDynamicSharedMemorySize, SMEM);
    cudaFuncSetAttribute(mma_gemm<2, true>,
                         cudaFuncAttributeMaxDynamicSharedMemorySize, SMEM);

    convert_x<<<32768, 256>>>(x);
    convert_w<<<256, 256>>>(w_qkv, w_out);
    mma_gemm<6, false><<<dim3(6, 1024), 256, SMEM>>>(b_qkv, nullptr);
    attn_kernel<<<dim3(2048, 8), 128>>>(pos);
    mma_gemm<2, true><<<dim3(2, 1024), 256, SMEM>>>(b_out, out);
}